// round 7
// baseline (speedup 1.0000x reference)
#include <cuda_runtime.h>
#include <math.h>
#include <stdint.h>

#define BATCHN 4
#define SEQL   2048
#define DM     1024
#define DI     2048
#define DS     16
#define RK     64
#define PD     96
#define NTOK   (BATCHN*SEQL)   // 8192
#define NC     32              // scan chunks
#define CH     64              // chunk length (NC*CH == SEQL)
#define NSPLIT 8               // split-K for x_proj

// ---------------- scratch (static device allocation; no cudaMalloc) ----------
__device__ float g_xnorm[(size_t)NTOK*DM];        // 32 MB
__device__ float g_xz   [(size_t)NTOK*2*DI];      // 128 MB
__device__ float g_u    [(size_t)NTOK*DI];        // 64 MB
__device__ float g_xdbl [(size_t)NTOK*PD];        // 3 MB
__device__ float g_part [(size_t)NSPLIT*NTOK*PD]; // 25 MB (split-K partials)
__device__ float g_dt   [(size_t)NTOK*DI];        // 64 MB
__device__ float g_y    [(size_t)NTOK*DI];        // 64 MB
__device__ float g_A    [DI*DS];
// scan state, layout [b][c][s][d] for coalesced access
__device__ float g_hend  [(size_t)BATCHN*NC*DS*DI];
__device__ float g_P     [(size_t)BATCHN*NC*DS*DI];
__device__ float g_hstart[(size_t)BATCHN*NC*DS*DI];
__device__ int   g_fast;

// ---------------- small helpers ----------------
__device__ __forceinline__ float softplusf(float v) {
    return v > 20.0f ? v : log1pf(__expf(v));
}
__device__ __forceinline__ float siluf(float v) {
    return v / (1.0f + __expf(-v));
}

// ---------------- prep: flag + A = -exp(A_log) ----------------
__global__ void k_init() { g_fast = 1; }

__global__ void k_prepA(const float* __restrict__ A_log) {
    int i = blockIdx.x * blockDim.x + threadIdx.x;
    if (i < DI * DS) {
        float a = -__expf(A_log[i]);
        g_A[i] = a;
        int s = i & (DS - 1);
        float expect = -(float)(s + 1);
        if (fabsf(a - expect) > 1e-3f * (float)(s + 1))
            atomicExch(&g_fast, 0);
    }
}

// ---------------- RMSNorm: one block per token ----------------
__global__ __launch_bounds__(256)
void k_rmsnorm(const float* __restrict__ x, const float* __restrict__ w) {
    int row = blockIdx.x;
    const float4* xr = reinterpret_cast<const float4*>(x) + (size_t)row * (DM / 4);
    float4 v = xr[threadIdx.x];
    float ss = v.x * v.x + v.y * v.y + v.z * v.z + v.w * v.w;
#pragma unroll
    for (int o = 16; o > 0; o >>= 1) ss += __shfl_xor_sync(0xffffffffu, ss, o);
    __shared__ float red[8];
    __shared__ float scale_s;
    int wid = threadIdx.x >> 5;
    if ((threadIdx.x & 31) == 0) red[wid] = ss;
    __syncthreads();
    if (threadIdx.x == 0) {
        float t = 0.f;
#pragma unroll
        for (int i = 0; i < 8; i++) t += red[i];
        scale_s = rsqrtf(t * (1.0f / (float)DM) + 1.1920929e-7f);
    }
    __syncthreads();
    float s = scale_s;
    float4 wv = reinterpret_cast<const float4*>(w)[threadIdx.x];
    float4 o;
    o.x = v.x * s * wv.x; o.y = v.y * s * wv.y;
    o.z = v.z * s * wv.z; o.w = v.w * s * wv.w;
    reinterpret_cast<float4*>(g_xnorm)[(size_t)row * (DM / 4) + threadIdx.x] = o;
}

// ---------------- generic SGEMM: C[M,N] = A[M,K] * W[N,K]^T ----------------
// 128x128 tile, BK=16, 256 threads, 8x8 per thread, register-prefetch pipeline.
// grid.z = split-K slices (K = per-slice K, koff = z*K, C += z*cSplitStride).
// EPI: 0 = plain, 1 = +bias then softplus (EP = bias[N]), 2 = +residual (EP same layout as C)
template<int EPI>
__global__ __launch_bounds__(256, 2)
void sgemm_kernel(const float* __restrict__ A, int lda,
                  const float* __restrict__ W, int ldw,
                  float* __restrict__ C, int ldc,
                  int M, int N, int K,
                  const float* __restrict__ EP,
                  size_t cSplitStride)
{
    __shared__ float sA[16 * 128];
    __shared__ float sB[16 * 128];
    const int tid = threadIdx.x;
    const int tx = tid & 15, ty = tid >> 4;
    const int mBase = blockIdx.y * 128;
    const int nBase = blockIdx.x * 128;
    const int koff = blockIdx.z * K;
    C += (size_t)blockIdx.z * cSplitStride;

    const int r0 = tid >> 2;   // 0..63
    const int kq = tid & 3;    // which float4 along K

    const float* Ap0 = A + (size_t)(mBase + r0) * lda + koff + kq * 4;
    const float* Ap1 = Ap0 + (size_t)64 * lda;
    const int n0 = nBase + r0, n1 = n0 + 64;
    const float* Wp0 = W + (size_t)n0 * ldw + koff + kq * 4;
    const float* Wp1 = W + (size_t)n1 * ldw + koff + kq * 4;
    const bool v0 = n0 < N, v1 = n1 < N;

    float acc[8][8];
#pragma unroll
    for (int i = 0; i < 8; i++)
#pragma unroll
        for (int j = 0; j < 8; j++) acc[i][j] = 0.f;

    const float4 zero4 = make_float4(0.f, 0.f, 0.f, 0.f);
    float4 pa0 = *(const float4*)Ap0;
    float4 pa1 = *(const float4*)Ap1;
    float4 pb0 = v0 ? *(const float4*)Wp0 : zero4;
    float4 pb1 = v1 ? *(const float4*)Wp1 : zero4;

    const int nk = K / 16;
    for (int kt = 0; kt < nk; kt++) {
        __syncthreads();
        const int c0 = kq * 4;
        sA[(c0 + 0) * 128 + r0] = pa0.x;  sA[(c0 + 1) * 128 + r0] = pa0.y;
        sA[(c0 + 2) * 128 + r0] = pa0.z;  sA[(c0 + 3) * 128 + r0] = pa0.w;
        sA[(c0 + 0) * 128 + r0 + 64] = pa1.x;  sA[(c0 + 1) * 128 + r0 + 64] = pa1.y;
        sA[(c0 + 2) * 128 + r0 + 64] = pa1.z;  sA[(c0 + 3) * 128 + r0 + 64] = pa1.w;
        sB[(c0 + 0) * 128 + r0] = pb0.x;  sB[(c0 + 1) * 128 + r0] = pb0.y;
        sB[(c0 + 2) * 128 + r0] = pb0.z;  sB[(c0 + 3) * 128 + r0] = pb0.w;
        sB[(c0 + 0) * 128 + r0 + 64] = pb1.x;  sB[(c0 + 1) * 128 + r0 + 64] = pb1.y;
        sB[(c0 + 2) * 128 + r0 + 64] = pb1.z;  sB[(c0 + 3) * 128 + r0 + 64] = pb1.w;
        __syncthreads();
        if (kt + 1 < nk) {
            Ap0 += 16; Ap1 += 16; Wp0 += 16; Wp1 += 16;
            pa0 = *(const float4*)Ap0;
            pa1 = *(const float4*)Ap1;
            pb0 = v0 ? *(const float4*)Wp0 : zero4;
            pb1 = v1 ? *(const float4*)Wp1 : zero4;
        }
#pragma unroll
        for (int k = 0; k < 16; k++) {
            float4 a0 = *(const float4*)&sA[k * 128 + ty * 8];
            float4 a1 = *(const float4*)&sA[k * 128 + ty * 8 + 4];
            float4 b0 = *(const float4*)&sB[k * 128 + tx * 8];
            float4 b1 = *(const float4*)&sB[k * 128 + tx * 8 + 4];
            float ar[8] = {a0.x, a0.y, a0.z, a0.w, a1.x, a1.y, a1.z, a1.w};
            float br[8] = {b0.x, b0.y, b0.z, b0.w, b1.x, b1.y, b1.z, b1.w};
#pragma unroll
            for (int i = 0; i < 8; i++)
#pragma unroll
                for (int j = 0; j < 8; j++)
                    acc[i][j] = fmaf(ar[i], br[j], acc[i][j]);
        }
    }

#pragma unroll
    for (int i = 0; i < 8; i++) {
        const int row = mBase + ty * 8 + i;
#pragma unroll
        for (int jj = 0; jj < 8; jj += 4) {
            const int col = nBase + tx * 8 + jj;
            if (col < N) {
                float4 v = make_float4(acc[i][jj], acc[i][jj + 1], acc[i][jj + 2], acc[i][jj + 3]);
                if (EPI == 1) {
                    float4 bia = *(const float4*)&EP[col];
                    v.x = softplusf(v.x + bia.x);
                    v.y = softplusf(v.y + bia.y);
                    v.z = softplusf(v.z + bia.z);
                    v.w = softplusf(v.w + bia.w);
                } else if (EPI == 2) {
                    float4 r = *(const float4*)&EP[(size_t)row * ldc + col];
                    v.x += r.x; v.y += r.y; v.z += r.z; v.w += r.w;
                }
                *(float4*)&C[(size_t)row * ldc + col] = v;
            }
        }
    }
}

// ---------------- split-K reduce for x_proj ----------------
__global__ void k_reduce_xdbl() {
    int i = blockIdx.x * blockDim.x + threadIdx.x;
    if (i < NTOK * PD) {
        float s = 0.f;
#pragma unroll
        for (int ks = 0; ks < NSPLIT; ks++) s += g_part[(size_t)ks * NTOK * PD + i];
        g_xdbl[i] = s;
    }
}

// ---------------- causal depthwise conv1d + SiLU ----------------
__global__ void k_conv(const float* __restrict__ cw, const float* __restrict__ cb) {
    int i = blockIdx.x * blockDim.x + threadIdx.x;
    if (i >= NTOK * (DI / 4)) return;
    int dq = i % (DI / 4);
    int t  = i / (DI / 4);
    int d4 = dq * 4;
    int b = t >> 11, l = t & (SEQL - 1);
    float4 acc = *(const float4*)&cb[d4];
    float wreg[4][4];
#pragma unroll
    for (int r = 0; r < 4; r++) {
        float4 wr = *(const float4*)&cw[(d4 + r) * 4];
        wreg[r][0] = wr.x; wreg[r][1] = wr.y; wreg[r][2] = wr.z; wreg[r][3] = wr.w;
    }
#pragma unroll
    for (int j = 0; j < 4; j++) {
        int lj = l - 3 + j;
        if (lj >= 0) {
            float4 xv = *(const float4*)&g_xz[(size_t)(b * SEQL + lj) * (2 * DI) + d4];
            acc.x = fmaf(xv.x, wreg[0][j], acc.x);
            acc.y = fmaf(xv.y, wreg[1][j], acc.y);
            acc.z = fmaf(xv.z, wreg[2][j], acc.z);
            acc.w = fmaf(xv.w, wreg[3][j], acc.w);
        }
    }
    float4 o;
    o.x = siluf(acc.x); o.y = siluf(acc.y); o.z = siluf(acc.z); o.w = siluf(acc.w);
    *(float4*)&g_u[(size_t)t * DI + d4] = o;
}

// ---------------- scan phase 1: per-chunk local recurrence (h0=0) ----------------
// block: 128 threads, 2 channels each (256 d); grid (DI/256, B, NC)
__global__ __launch_bounds__(128)
void k_scan1() {
    __shared__ float sBC[CH * 32];   // [t][0..15]=B, [t][16..31]=C
    const int b = blockIdx.y, c = blockIdx.z;
    const int l0 = c * CH;
    const int tid = threadIdx.x;
    for (int i = tid; i < CH * 8; i += 128) {
        int r = i >> 3, cq = i & 7;
        *(float4*)&sBC[r * 32 + cq * 4] =
            *(const float4*)&g_xdbl[(size_t)(b * SEQL + l0 + r) * PD + 64 + cq * 4];
    }
    __syncthreads();
    const int d0 = blockIdx.x * 256 + tid * 2;
    float h0[DS], h1[DS];
#pragma unroll
    for (int s = 0; s < DS; s++) { h0[s] = 0.f; h1[s] = 0.f; }
    const float* dtp = &g_dt[(size_t)(b * SEQL + l0) * DI + d0];
    const float* up  = &g_u [(size_t)(b * SEQL + l0) * DI + d0];
    const size_t sb = (size_t)(b * NC + c) * DS * DI + d0;   // layout [b][c][s][d]
    const int fast = g_fast;

    if (fast) {
        float q0 = 1.f, q1 = 1.f;
        for (int t = 0; t < CH; t++) {
            float2 dt2 = *(const float2*)(dtp + (size_t)t * DI);
            float2 u2  = *(const float2*)(up  + (size_t)t * DI);
            float e0 = __expf(-dt2.x), e1 = __expf(-dt2.y);
            float w0 = dt2.x * u2.x,   w1 = dt2.y * u2.y;
            q0 *= e0; q1 *= e1;
            float p0 = e0, p1 = e1;
#pragma unroll
            for (int s = 0; s < DS; s++) {
                float Bs = sBC[t * 32 + s];
                h0[s] = fmaf(p0, h0[s], w0 * Bs);
                h1[s] = fmaf(p1, h1[s], w1 * Bs);
                p0 *= e0; p1 *= e1;
            }
        }
#pragma unroll
        for (int s = 0; s < DS; s++)
            *(float2*)&g_hend[sb + (size_t)s * DI] = make_float2(h0[s], h1[s]);
        float pp0 = q0, pp1 = q1;
#pragma unroll
        for (int s = 0; s < DS; s++) {
            *(float2*)&g_P[sb + (size_t)s * DI] = make_float2(pp0, pp1);
            pp0 *= q0; pp1 *= q1;
        }
    } else {
        float a0[DS], a1[DS], P0[DS], P1[DS];
#pragma unroll
        for (int s = 0; s < DS; s++) {
            a0[s] = g_A[d0 * DS + s];
            a1[s] = g_A[(d0 + 1) * DS + s];
            P0[s] = 1.f; P1[s] = 1.f;
        }
        for (int t = 0; t < CH; t++) {
            float2 dt2 = *(const float2*)(dtp + (size_t)t * DI);
            float2 u2  = *(const float2*)(up  + (size_t)t * DI);
            float w0 = dt2.x * u2.x, w1 = dt2.y * u2.y;
#pragma unroll
            for (int s = 0; s < DS; s++) {
                float Bs = sBC[t * 32 + s];
                float dA0 = __expf(dt2.x * a0[s]);
                float dA1 = __expf(dt2.y * a1[s]);
                h0[s] = fmaf(dA0, h0[s], w0 * Bs);
                h1[s] = fmaf(dA1, h1[s], w1 * Bs);
                P0[s] *= dA0; P1[s] *= dA1;
            }
        }
#pragma unroll
        for (int s = 0; s < DS; s++) {
            *(float2*)&g_hend[sb + (size_t)s * DI] = make_float2(h0[s], h1[s]);
            *(float2*)&g_P  [sb + (size_t)s * DI] = make_float2(P0[s], P1[s]);
        }
    }
}

// ---------------- scan phase 2: combine chunk states ----------------
__global__ void k_scan2() {
    int idx = blockIdx.x * blockDim.x + threadIdx.x;   // < B*DS*DI
    if (idx >= BATCHN * DS * DI) return;
    int d = idx & (DI - 1);
    int s = (idx >> 11) & (DS - 1);
    int b = idx >> 15;
    float hs = 0.f;
    size_t base = ((size_t)(b * NC) * DS + s) * DI + d;
    const size_t cstride = (size_t)DS * DI;
    for (int c = 0; c < NC; c++) {
        size_t off = base + (size_t)c * cstride;
        g_hstart[off] = hs;
        hs = g_P[off] * hs + g_hend[off];
    }
}

// ---------------- scan phase 3: recompute with correct h0, emit y ----------------
__global__ __launch_bounds__(128)
void k_scan3(const float* __restrict__ Dp_) {
    __shared__ float sBC[CH * 32];
    const int b = blockIdx.y, c = blockIdx.z;
    const int l0 = c * CH;
    const int tid = threadIdx.x;
    for (int i = tid; i < CH * 8; i += 128) {
        int r = i >> 3, cq = i & 7;
        *(float4*)&sBC[r * 32 + cq * 4] =
            *(const float4*)&g_xdbl[(size_t)(b * SEQL + l0 + r) * PD + 64 + cq * 4];
    }
    __syncthreads();
    const int d0 = blockIdx.x * 256 + tid * 2;
    const size_t sb = (size_t)(b * NC + c) * DS * DI + d0;
    float h0[DS], h1[DS];
#pragma unroll
    for (int s = 0; s < DS; s++) {
        float2 hv = *(const float2*)&g_hstart[sb + (size_t)s * DI];
        h0[s] = hv.x; h1[s] = hv.y;
    }
    float2 Dv = *(const float2*)&Dp_[d0];
    const float* dtp = &g_dt[(size_t)(b * SEQL + l0) * DI + d0];
    const float* up  = &g_u [(size_t)(b * SEQL + l0) * DI + d0];
    const float* zp  = &g_xz[(size_t)(b * SEQL + l0) * (2 * DI) + DI + d0];
    float* yp        = &g_y [(size_t)(b * SEQL + l0) * DI + d0];
    const int fast = g_fast;

    if (fast) {
        for (int t = 0; t < CH; t++) {
            float2 dt2 = *(const float2*)(dtp + (size_t)t * DI);
            float2 u2  = *(const float2*)(up  + (size_t)t * DI);
            float e0 = __expf(-dt2.x), e1 = __expf(-dt2.y);
            float w0 = dt2.x * u2.x,   w1 = dt2.y * u2.y;
            float p0 = e0, p1 = e1;
            float y0 = 0.f, y1 = 0.f;
#pragma unroll
            for (int s = 0; s < DS; s++) {
                float Bs = sBC[t * 32 + s];
                float Cs = sBC[t * 32 + 16 + s];
                h0[s] = fmaf(p0, h0[s], w0 * Bs);
                h1[s] = fmaf(p1, h1[s], w1 * Bs);
                y0 = fmaf(h0[s], Cs, y0);
                y1 = fmaf(h1[s], Cs, y1);
                p0 *= e0; p1 *= e1;
            }
            float2 z2 = *(const float2*)(zp + (size_t)t * (2 * DI));
            float o0 = (y0 + Dv.x * u2.x) * siluf(z2.x);
            float o1 = (y1 + Dv.y * u2.y) * siluf(z2.y);
            *(float2*)(yp + (size_t)t * DI) = make_float2(o0, o1);
        }
    } else {
        float a0[DS], a1[DS];
#pragma unroll
        for (int s = 0; s < DS; s++) {
            a0[s] = g_A[d0 * DS + s];
            a1[s] = g_A[(d0 + 1) * DS + s];
        }
        for (int t = 0; t < CH; t++) {
            float2 dt2 = *(const float2*)(dtp + (size_t)t * DI);
            float2 u2  = *(const float2*)(up  + (size_t)t * DI);
            float w0 = dt2.x * u2.x, w1 = dt2.y * u2.y;
            float y0 = 0.f, y1 = 0.f;
#pragma unroll
            for (int s = 0; s < DS; s++) {
                float Bs = sBC[t * 32 + s];
                float Cs = sBC[t * 32 + 16 + s];
                float dA0 = __expf(dt2.x * a0[s]);
                float dA1 = __expf(dt2.y * a1[s]);
                h0[s] = fmaf(dA0, h0[s], w0 * Bs);
                h1[s] = fmaf(dA1, h1[s], w1 * Bs);
                y0 = fmaf(h0[s], Cs, y0);
                y1 = fmaf(h1[s], Cs, y1);
            }
            float2 z2 = *(const float2*)(zp + (size_t)t * (2 * DI));
            float o0 = (y0 + Dv.x * u2.x) * siluf(z2.x);
            float o1 = (y1 + Dv.y * u2.y) * siluf(z2.y);
            *(float2*)(yp + (size_t)t * DI) = make_float2(o0, o1);
        }
    }
}

// ---------------- launcher ----------------
extern "C" void kernel_launch(void* const* d_in, const int* in_sizes, int n_in,
                              void* d_out, int out_size) {
    (void)in_sizes; (void)n_in; (void)out_size;
    const float* x          = (const float*)d_in[0];
    const float* norm_w     = (const float*)d_in[1];
    const float* in_proj_w  = (const float*)d_in[2];
    const float* conv_w     = (const float*)d_in[3];
    const float* conv_b     = (const float*)d_in[4];
    const float* x_proj_w   = (const float*)d_in[5];
    const float* dt_proj_w  = (const float*)d_in[6];
    const float* dt_proj_b  = (const float*)d_in[7];
    const float* A_log      = (const float*)d_in[8];
    const float* D_param    = (const float*)d_in[9];
    const float* out_proj_w = (const float*)d_in[10];
    float* out = (float*)d_out;

    float *p_xnorm, *p_xz, *p_u, *p_xdbl, *p_part, *p_dt, *p_y;
    cudaGetSymbolAddress((void**)&p_xnorm, g_xnorm);
    cudaGetSymbolAddress((void**)&p_xz,    g_xz);
    cudaGetSymbolAddress((void**)&p_u,     g_u);
    cudaGetSymbolAddress((void**)&p_xdbl,  g_xdbl);
    cudaGetSymbolAddress((void**)&p_part,  g_part);
    cudaGetSymbolAddress((void**)&p_dt,    g_dt);
    cudaGetSymbolAddress((void**)&p_y,     g_y);

    k_init<<<1, 1>>>();
    k_prepA<<<(DI * DS + 255) / 256, 256>>>(A_log);
    k_rmsnorm<<<NTOK, 256>>>(x, norm_w);

    // xz = x_norm @ in_proj_w^T   [8192 x 4096]
    sgemm_kernel<0><<<dim3(2 * DI / 128, NTOK / 128, 1), 256>>>(
        p_xnorm, DM, in_proj_w, DM, p_xz, 2 * DI, NTOK, 2 * DI, DM, nullptr, 0);

    // u = silu(conv1d(x_in) + b)
    k_conv<<<(NTOK * (DI / 4)) / 256, 256>>>(conv_w, conv_b);

    // x_dbl = u @ x_proj_w^T   [8192 x 96]  (split-K=8 -> partials -> reduce)
    sgemm_kernel<0><<<dim3(1, NTOK / 128, NSPLIT), 256>>>(
        p_u, DI, x_proj_w, DI, p_part, PD, NTOK, PD, DI / NSPLIT,
        nullptr, (size_t)NTOK * PD);
    k_reduce_xdbl<<<(NTOK * PD) / 256, 256>>>();

    // dt = softplus(x_dbl[:, :64] @ dt_proj_w^T + b)   [8192 x 2048]
    sgemm_kernel<1><<<dim3(DI / 128, NTOK / 128, 1), 256>>>(
        p_xdbl, PD, dt_proj_w, RK, p_dt, DI, NTOK, DI, RK, dt_proj_b, 0);

    // selective scan (chunked parallel) + fused (+D*u)*silu(z)
    k_scan1<<<dim3(DI / 256, BATCHN, NC), 128>>>();
    k_scan2<<<(BATCHN * DS * DI) / 256, 256>>>();
    k_scan3<<<dim3(DI / 256, BATCHN, NC), 128>>>(D_param);

    // out = x + y @ out_proj_w^T   [8192 x 1024]
    sgemm_kernel<2><<<dim3(DM / 128, NTOK / 128, 1), 256>>>(
        p_y, DI, out_proj_w, DI, out, DM, NTOK, DM, DI, x, 0);
}

// round 11
// speedup vs baseline: 5.7810x; 5.7810x over previous
#include <cuda_runtime.h>
#include <cuda_bf16.h>
#include <math.h>
#include <stdint.h>

#define BATCHN 4
#define SEQL   2048
#define DM     1024
#define DI     2048
#define DS     16
#define RK     64
#define PD     96
#define NTOK   (BATCHN*SEQL)   // 8192
#define NC     32              // scan chunks
#define CH     64              // chunk length
#define NSPLIT 8               // split-K for x_proj

// ---------------- scratch (static device allocation; no cudaMalloc) ----------
__device__ __align__(16) float g_xz   [(size_t)NTOK*2*DI];      // 128 MB
__device__ __align__(16) float g_u    [(size_t)NTOK*DI];        // 64 MB
__device__ __align__(16) float g_xdbl [(size_t)NTOK*PD];
__device__ __align__(16) float g_part [(size_t)NSPLIT*NTOK*PD];
__device__ __align__(16) float g_dt   [(size_t)NTOK*DI];        // 64 MB
__device__ float g_A    [DI*DS];
__device__ float g_hend  [(size_t)BATCHN*NC*DS*DI];
__device__ float g_P     [(size_t)BATCHN*NC*DS*DI];
__device__ float g_hstart[(size_t)BATCHN*NC*DS*DI];
__device__ int   g_fast;
// bf16 buffers for tensor-core GEMMs
__device__ __align__(16) __nv_bfloat16 g_xnb [(size_t)NTOK*DM];     // 16 MB
__device__ __align__(16) __nv_bfloat16 g_yb  [(size_t)NTOK*DI];     // 32 MB
__device__ __align__(16) __nv_bfloat16 g_winb[(size_t)2*DI*DM];     // 8 MB
__device__ __align__(16) __nv_bfloat16 g_woutb[(size_t)DM*DI];      // 4 MB

// ---------------- helpers ----------------
__device__ __forceinline__ float softplusf(float v) {
    return v > 20.0f ? v : log1pf(__expf(v));
}
__device__ __forceinline__ float siluf(float v) {
    return v / (1.0f + __expf(-v));
}
__device__ __forceinline__ uint32_t smem_u32(const void* p) {
    uint32_t a;
    asm("{ .reg .u64 t; cvta.to.shared.u64 t, %1; cvt.u32.u64 %0, t; }" : "=r"(a) : "l"(p));
    return a;
}
__device__ __forceinline__ void cp16(uint32_t sm, const void* g) {
    asm volatile("cp.async.cg.shared.global [%0], [%1], 16;" :: "r"(sm), "l"(g));
}
__device__ __forceinline__ void ldsm4(uint32_t* r, uint32_t addr) {
    asm volatile("ldmatrix.sync.aligned.m8n8.x4.shared.b16 {%0,%1,%2,%3}, [%4];"
        : "=r"(r[0]), "=r"(r[1]), "=r"(r[2]), "=r"(r[3]) : "r"(addr));
}
__device__ __forceinline__ void mma16816(float* c, const uint32_t* a, uint32_t b0, uint32_t b1) {
    asm volatile("mma.sync.aligned.m16n8k16.row.col.f32.bf16.bf16.f32 "
        "{%0,%1,%2,%3}, {%4,%5,%6,%7}, {%8,%9}, {%0,%1,%2,%3};"
        : "+f"(c[0]), "+f"(c[1]), "+f"(c[2]), "+f"(c[3])
        : "r"(a[0]), "r"(a[1]), "r"(a[2]), "r"(a[3]), "r"(b0), "r"(b1));
}

// ---------------- bf16 HGEMM (mma.sync): C[M,N] fp32 = A[M,K]bf16 @ W[N,K]bf16^T
// 128x128 tile, BK=64 (128B swizzled rows), double-buffered cp.async.
// 8 warps as 2(M)x4(N); warp tile 64x32. EPI: 0 = plain, 2 = +residual.
#define HG_SMEM 65536
template<int EPI>
__global__ __launch_bounds__(256, 2)
void hgemm(const __nv_bfloat16* __restrict__ A, int lda,
           const __nv_bfloat16* __restrict__ W, int ldw,
           float* __restrict__ C, int ldc, int K,
           const float* __restrict__ resid)
{
    extern __shared__ char smem_raw[];
    const uint32_t abase = smem_u32(smem_raw);          // A bufs: 2 x 16KB
    const uint32_t bbase = abase + 32768;               // B bufs: 2 x 16KB
    const int tid = threadIdx.x, wid = tid >> 5, lane = tid & 31;
    const int mBase = blockIdx.y * 128, nBase = blockIdx.x * 128;
    const int warpM = (wid >> 2) * 64;   // 0 or 64
    const int warpN = (wid & 3) * 32;    // 0,32,64,96

    float acc[4][4][4];
#pragma unroll
    for (int i = 0; i < 4; i++)
#pragma unroll
        for (int j = 0; j < 4; j++)
#pragma unroll
            for (int q = 0; q < 4; q++) acc[i][j][q] = 0.f;

    const int nk = K / 64;

    // stage loader: fills buffer (kt&1) with A/B K-chunk kt, SW128 swizzle
    auto load_stage = [&](int kt) {
        const int b = kt & 1;
        const uint32_t aB = abase + b * 16384;
        const uint32_t bB = bbase + b * 16384;
        const __nv_bfloat16* Ag = A + (size_t)mBase * lda + kt * 64;
        const __nv_bfloat16* Wg = W + (size_t)nBase * ldw + kt * 64;
#pragma unroll
        for (int p = 0; p < 4; p++) {
            int idx = p * 256 + tid;           // 0..1023
            int row = idx >> 3, u = idx & 7;
            int su = row * 8 + (u ^ (row & 7));
            cp16(aB + su * 16, Ag + (size_t)row * lda + u * 8);
            cp16(bB + su * 16, Wg + (size_t)row * ldw + u * 8);
        }
        asm volatile("cp.async.commit_group;" ::: "memory");
    };

    load_stage(0);
    for (int kt = 0; kt < nk; kt++) {
        if (kt + 1 < nk) {
            load_stage(kt + 1);
            asm volatile("cp.async.wait_group 1;" ::: "memory");
        } else {
            asm volatile("cp.async.wait_group 0;" ::: "memory");
        }
        __syncthreads();
        const int b = kt & 1;
        const uint32_t aB = abase + b * 16384;
        const uint32_t bB = bbase + b * 16384;
#pragma unroll
        for (int ks = 0; ks < 4; ks++) {
            uint32_t afr[4][4];
#pragma unroll
            for (int mt = 0; mt < 4; mt++) {
                int r = warpM + mt * 16 + (lane & 15);
                int u = ks * 2 + (lane >> 4);
                ldsm4(afr[mt], aB + (r * 8 + (u ^ (r & 7))) * 16);
            }
            uint32_t bfr[2][4];
#pragma unroll
            for (int nt = 0; nt < 2; nt++) {
                int r = warpN + nt * 16 + (lane & 15);
                int u = ks * 2 + (lane >> 4);
                ldsm4(bfr[nt], bB + (r * 8 + (u ^ (r & 7))) * 16);
            }
#pragma unroll
            for (int mt = 0; mt < 4; mt++)
#pragma unroll
                for (int j = 0; j < 4; j++)
                    mma16816(acc[mt][j], afr[mt], bfr[j >> 1][j & 1], bfr[j >> 1][(j & 1) + 2]);
        }
        __syncthreads();
    }

    // epilogue: C frag layout c0,c1: (row=lane/4, col=2*(lane%4)+{0,1}); c2,c3: row+8
#pragma unroll
    for (int mt = 0; mt < 4; mt++) {
        const int row0 = mBase + warpM + mt * 16 + (lane >> 2);
        const int row1 = row0 + 8;
#pragma unroll
        for (int j = 0; j < 4; j++) {
            const int col = nBase + warpN + j * 8 + (lane & 3) * 2;
            float2 v0 = make_float2(acc[mt][j][0], acc[mt][j][1]);
            float2 v1 = make_float2(acc[mt][j][2], acc[mt][j][3]);
            if (EPI == 2) {
                float2 r0 = *(const float2*)&resid[(size_t)row0 * ldc + col];
                float2 r1 = *(const float2*)&resid[(size_t)row1 * ldc + col];
                v0.x += r0.x; v0.y += r0.y; v1.x += r1.x; v1.y += r1.y;
            }
            *(float2*)&C[(size_t)row0 * ldc + col] = v0;
            *(float2*)&C[(size_t)row1 * ldc + col] = v1;
        }
    }
}

// ---------------- prep ----------------
__global__ void k_init() { g_fast = 1; }

__global__ void k_prepA(const float* __restrict__ A_log) {
    int i = blockIdx.x * blockDim.x + threadIdx.x;
    if (i < DI * DS) {
        float a = -__expf(A_log[i]);
        g_A[i] = a;
        int s = i & (DS - 1);
        float expect = -(float)(s + 1);
        if (fabsf(a - expect) > 1e-3f * (float)(s + 1))
            atomicExch(&g_fast, 0);
    }
}

// fp32 -> bf16 conversion (n divisible by 4)
__global__ void k_f2b(const float* __restrict__ src, __nv_bfloat16* __restrict__ dst, int n4) {
    int i = blockIdx.x * blockDim.x + threadIdx.x;
    if (i < n4) {
        float4 v = ((const float4*)src)[i];
        __nv_bfloat162 lo = __floats2bfloat162_rn(v.x, v.y);
        __nv_bfloat162 hi = __floats2bfloat162_rn(v.z, v.w);
        uint2 o; o.x = *(uint32_t*)&lo; o.y = *(uint32_t*)&hi;
        ((uint2*)dst)[i] = o;
    }
}

// ---------------- RMSNorm -> bf16 ----------------
__global__ __launch_bounds__(256)
void k_rmsnorm(const float* __restrict__ x, const float* __restrict__ w) {
    int row = blockIdx.x;
    const float4* xr = reinterpret_cast<const float4*>(x) + (size_t)row * (DM / 4);
    float4 v = xr[threadIdx.x];
    float ss = v.x * v.x + v.y * v.y + v.z * v.z + v.w * v.w;
#pragma unroll
    for (int o = 16; o > 0; o >>= 1) ss += __shfl_xor_sync(0xffffffffu, ss, o);
    __shared__ float red[8];
    __shared__ float scale_s;
    int wid = threadIdx.x >> 5;
    if ((threadIdx.x & 31) == 0) red[wid] = ss;
    __syncthreads();
    if (threadIdx.x == 0) {
        float t = 0.f;
#pragma unroll
        for (int i = 0; i < 8; i++) t += red[i];
        scale_s = rsqrtf(t * (1.0f / (float)DM) + 1.1920929e-7f);
    }
    __syncthreads();
    float s = scale_s;
    float4 wv = reinterpret_cast<const float4*>(w)[threadIdx.x];
    __nv_bfloat162 lo = __floats2bfloat162_rn(v.x * s * wv.x, v.y * s * wv.y);
    __nv_bfloat162 hi = __floats2bfloat162_rn(v.z * s * wv.z, v.w * s * wv.w);
    uint2 o; o.x = *(uint32_t*)&lo; o.y = *(uint32_t*)&hi;
    ((uint2*)g_xnb)[(size_t)row * (DM / 4) + threadIdx.x] = o;
}

// ---------------- fp32 SGEMM (small GEMMs: x_proj split-K, dt_proj) ----------
template<int EPI>
__global__ __launch_bounds__(256, 2)
void sgemm_kernel(const float* __restrict__ A, int lda,
                  const float* __restrict__ W, int ldw,
                  float* __restrict__ C, int ldc,
                  int M, int N, int K,
                  const float* __restrict__ EP,
                  size_t cSplitStride)
{
    __shared__ float sA[16 * 128];
    __shared__ float sB[16 * 128];
    const int tid = threadIdx.x;
    const int tx = tid & 15, ty = tid >> 4;
    const int mBase = blockIdx.y * 128;
    const int nBase = blockIdx.x * 128;
    const int koff = blockIdx.z * K;
    C += (size_t)blockIdx.z * cSplitStride;

    const int r0 = tid >> 2;
    const int kq = tid & 3;

    const float* Ap0 = A + (size_t)(mBase + r0) * lda + koff + kq * 4;
    const float* Ap1 = Ap0 + (size_t)64 * lda;
    const int n0 = nBase + r0, n1 = n0 + 64;
    const float* Wp0 = W + (size_t)n0 * ldw + koff + kq * 4;
    const float* Wp1 = W + (size_t)n1 * ldw + koff + kq * 4;
    const bool v0 = n0 < N, v1 = n1 < N;

    float acc[8][8];
#pragma unroll
    for (int i = 0; i < 8; i++)
#pragma unroll
        for (int j = 0; j < 8; j++) acc[i][j] = 0.f;

    const float4 zero4 = make_float4(0.f, 0.f, 0.f, 0.f);
    float4 pa0 = *(const float4*)Ap0;
    float4 pa1 = *(const float4*)Ap1;
    float4 pb0 = v0 ? *(const float4*)Wp0 : zero4;
    float4 pb1 = v1 ? *(const float4*)Wp1 : zero4;

    const int nk = K / 16;
    for (int kt = 0; kt < nk; kt++) {
        __syncthreads();
        const int c0 = kq * 4;
        sA[(c0 + 0) * 128 + r0] = pa0.x;  sA[(c0 + 1) * 128 + r0] = pa0.y;
        sA[(c0 + 2) * 128 + r0] = pa0.z;  sA[(c0 + 3) * 128 + r0] = pa0.w;
        sA[(c0 + 0) * 128 + r0 + 64] = pa1.x;  sA[(c0 + 1) * 128 + r0 + 64] = pa1.y;
        sA[(c0 + 2) * 128 + r0 + 64] = pa1.z;  sA[(c0 + 3) * 128 + r0 + 64] = pa1.w;
        sB[(c0 + 0) * 128 + r0] = pb0.x;  sB[(c0 + 1) * 128 + r0] = pb0.y;
        sB[(c0 + 2) * 128 + r0] = pb0.z;  sB[(c0 + 3) * 128 + r0] = pb0.w;
        sB[(c0 + 0) * 128 + r0 + 64] = pb1.x;  sB[(c0 + 1) * 128 + r0 + 64] = pb1.y;
        sB[(c0 + 2) * 128 + r0 + 64] = pb1.z;  sB[(c0 + 3) * 128 + r0 + 64] = pb1.w;
        __syncthreads();
        if (kt + 1 < nk) {
            Ap0 += 16; Ap1 += 16; Wp0 += 16; Wp1 += 16;
            pa0 = *(const float4*)Ap0;
            pa1 = *(const float4*)Ap1;
            pb0 = v0 ? *(const float4*)Wp0 : zero4;
            pb1 = v1 ? *(const float4*)Wp1 : zero4;
        }
#pragma unroll
        for (int k = 0; k < 16; k++) {
            float4 a0 = *(const float4*)&sA[k * 128 + ty * 8];
            float4 a1 = *(const float4*)&sA[k * 128 + ty * 8 + 4];
            float4 b0 = *(const float4*)&sB[k * 128 + tx * 8];
            float4 b1 = *(const float4*)&sB[k * 128 + tx * 8 + 4];
            float ar[8] = {a0.x, a0.y, a0.z, a0.w, a1.x, a1.y, a1.z, a1.w};
            float br[8] = {b0.x, b0.y, b0.z, b0.w, b1.x, b1.y, b1.z, b1.w};
#pragma unroll
            for (int i = 0; i < 8; i++)
#pragma unroll
                for (int j = 0; j < 8; j++)
                    acc[i][j] = fmaf(ar[i], br[j], acc[i][j]);
        }
    }

#pragma unroll
    for (int i = 0; i < 8; i++) {
        const int row = mBase + ty * 8 + i;
#pragma unroll
        for (int jj = 0; jj < 8; jj += 4) {
            const int col = nBase + tx * 8 + jj;
            if (col < N) {
                float4 v = make_float4(acc[i][jj], acc[i][jj + 1], acc[i][jj + 2], acc[i][jj + 3]);
                if (EPI == 1) {
                    float4 bia = *(const float4*)&EP[col];
                    v.x = softplusf(v.x + bia.x);
                    v.y = softplusf(v.y + bia.y);
                    v.z = softplusf(v.z + bia.z);
                    v.w = softplusf(v.w + bia.w);
                }
                *(float4*)&C[(size_t)row * ldc + col] = v;
            }
        }
    }
}

// ---------------- split-K reduce for x_proj ----------------
__global__ void k_reduce_xdbl() {
    int i = blockIdx.x * blockDim.x + threadIdx.x;
    if (i < NTOK * PD) {
        float s = 0.f;
#pragma unroll
        for (int ks = 0; ks < NSPLIT; ks++) s += g_part[(size_t)ks * NTOK * PD + i];
        g_xdbl[i] = s;
    }
}

// ---------------- causal depthwise conv1d + SiLU ----------------
__global__ void k_conv(const float* __restrict__ cw, const float* __restrict__ cb) {
    int i = blockIdx.x * blockDim.x + threadIdx.x;
    if (i >= NTOK * (DI / 4)) return;
    int dq = i % (DI / 4);
    int t  = i / (DI / 4);
    int d4 = dq * 4;
    int b = t >> 11, l = t & (SEQL - 1);
    float4 acc = *(const float4*)&cb[d4];
    float wreg[4][4];
#pragma unroll
    for (int r = 0; r < 4; r++) {
        float4 wr = *(const float4*)&cw[(d4 + r) * 4];
        wreg[r][0] = wr.x; wreg[r][1] = wr.y; wreg[r][2] = wr.z; wreg[r][3] = wr.w;
    }
#pragma unroll
    for (int j = 0; j < 4; j++) {
        int lj = l - 3 + j;
        if (lj >= 0) {
            float4 xv = *(const float4*)&g_xz[(size_t)(b * SEQL + lj) * (2 * DI) + d4];
            acc.x = fmaf(xv.x, wreg[0][j], acc.x);
            acc.y = fmaf(xv.y, wreg[1][j], acc.y);
            acc.z = fmaf(xv.z, wreg[2][j], acc.z);
            acc.w = fmaf(xv.w, wreg[3][j], acc.w);
        }
    }
    float4 o;
    o.x = siluf(acc.x); o.y = siluf(acc.y); o.z = siluf(acc.z); o.w = siluf(acc.w);
    *(float4*)&g_u[(size_t)t * DI + d4] = o;
}

// ---------------- scan phase 1 ----------------
__global__ __launch_bounds__(128)
void k_scan1() {
    __shared__ float sBC[CH * 32];
    const int b = blockIdx.y, c = blockIdx.z;
    const int l0 = c * CH;
    const int tid = threadIdx.x;
    for (int i = tid; i < CH * 8; i += 128) {
        int r = i >> 3, cq = i & 7;
        *(float4*)&sBC[r * 32 + cq * 4] =
            *(const float4*)&g_xdbl[(size_t)(b * SEQL + l0 + r) * PD + 64 + cq * 4];
    }
    __syncthreads();
    const int d0 = blockIdx.x * 256 + tid * 2;
    float h0[DS], h1[DS];
#pragma unroll
    for (int s = 0; s < DS; s++) { h0[s] = 0.f; h1[s] = 0.f; }
    const float* dtp = &g_dt[(size_t)(b * SEQL + l0) * DI + d0];
    const float* up  = &g_u [(size_t)(b * SEQL + l0) * DI + d0];
    const size_t sb = (size_t)(b * NC + c) * DS * DI + d0;
    const int fast = g_fast;

    if (fast) {
        float q0 = 1.f, q1 = 1.f;
        for (int t = 0; t < CH; t++) {
            float2 dt2 = *(const float2*)(dtp + (size_t)t * DI);
            float2 u2  = *(const float2*)(up  + (size_t)t * DI);
            float e0 = __expf(-dt2.x), e1 = __expf(-dt2.y);
            float w0 = dt2.x * u2.x,   w1 = dt2.y * u2.y;
            q0 *= e0; q1 *= e1;
            float p0 = e0, p1 = e1;
#pragma unroll
            for (int s = 0; s < DS; s++) {
                float Bs = sBC[t * 32 + s];
                h0[s] = fmaf(p0, h0[s], w0 * Bs);
                h1[s] = fmaf(p1, h1[s], w1 * Bs);
                p0 *= e0; p1 *= e1;
            }
        }
#pragma unroll
        for (int s = 0; s < DS; s++)
            *(float2*)&g_hend[sb + (size_t)s * DI] = make_float2(h0[s], h1[s]);
        float pp0 = q0, pp1 = q1;
#pragma unroll
        for (int s = 0; s < DS; s++) {
            *(float2*)&g_P[sb + (size_t)s * DI] = make_float2(pp0, pp1);
            pp0 *= q0; pp1 *= q1;
        }
    } else {
        float a0[DS], a1[DS], P0[DS], P1[DS];
#pragma unroll
        for (int s = 0; s < DS; s++) {
            a0[s] = g_A[d0 * DS + s];
            a1[s] = g_A[(d0 + 1) * DS + s];
            P0[s] = 1.f; P1[s] = 1.f;
        }
        for (int t = 0; t < CH; t++) {
            float2 dt2 = *(const float2*)(dtp + (size_t)t * DI);
            float2 u2  = *(const float2*)(up  + (size_t)t * DI);
            float w0 = dt2.x * u2.x, w1 = dt2.y * u2.y;
#pragma unroll
            for (int s = 0; s < DS; s++) {
                float Bs = sBC[t * 32 + s];
                float dA0 = __expf(dt2.x * a0[s]);
                float dA1 = __expf(dt2.y * a1[s]);
                h0[s] = fmaf(dA0, h0[s], w0 * Bs);
                h1[s] = fmaf(dA1, h1[s], w1 * Bs);
                P0[s] *= dA0; P1[s] *= dA1;
            }
        }
#pragma unroll
        for (int s = 0; s < DS; s++) {
            *(float2*)&g_hend[sb + (size_t)s * DI] = make_float2(h0[s], h1[s]);
            *(float2*)&g_P  [sb + (size_t)s * DI] = make_float2(P0[s], P1[s]);
        }
    }
}

// ---------------- scan phase 2 ----------------
__global__ void k_scan2() {
    int idx = blockIdx.x * blockDim.x + threadIdx.x;
    if (idx >= BATCHN * DS * DI) return;
    int d = idx & (DI - 1);
    int s = (idx >> 11) & (DS - 1);
    int b = idx >> 15;
    float hs = 0.f;
    size_t base = ((size_t)(b * NC) * DS + s) * DI + d;
    const size_t cstride = (size_t)DS * DI;
    for (int c = 0; c < NC; c++) {
        size_t off = base + (size_t)c * cstride;
        g_hstart[off] = hs;
        hs = g_P[off] * hs + g_hend[off];
    }
}

// ---------------- scan phase 3: emit y as bf16 ----------------
__global__ __launch_bounds__(128)
void k_scan3(const float* __restrict__ Dp_) {
    __shared__ float sBC[CH * 32];
    const int b = blockIdx.y, c = blockIdx.z;
    const int l0 = c * CH;
    const int tid = threadIdx.x;
    for (int i = tid; i < CH * 8; i += 128) {
        int r = i >> 3, cq = i & 7;
        *(float4*)&sBC[r * 32 + cq * 4] =
            *(const float4*)&g_xdbl[(size_t)(b * SEQL + l0 + r) * PD + 64 + cq * 4];
    }
    __syncthreads();
    const int d0 = blockIdx.x * 256 + tid * 2;
    const size_t sb = (size_t)(b * NC + c) * DS * DI + d0;
    float h0[DS], h1[DS];
#pragma unroll
    for (int s = 0; s < DS; s++) {
        float2 hv = *(const float2*)&g_hstart[sb + (size_t)s * DI];
        h0[s] = hv.x; h1[s] = hv.y;
    }
    float2 Dv = *(const float2*)&Dp_[d0];
    const float* dtp = &g_dt[(size_t)(b * SEQL + l0) * DI + d0];
    const float* up  = &g_u [(size_t)(b * SEQL + l0) * DI + d0];
    const float* zp  = &g_xz[(size_t)(b * SEQL + l0) * (2 * DI) + DI + d0];
    __nv_bfloat162* yp = (__nv_bfloat162*)&g_yb[(size_t)(b * SEQL + l0) * DI + d0];
    const int fast = g_fast;

    if (fast) {
        for (int t = 0; t < CH; t++) {
            float2 dt2 = *(const float2*)(dtp + (size_t)t * DI);
            float2 u2  = *(const float2*)(up  + (size_t)t * DI);
            float e0 = __expf(-dt2.x), e1 = __expf(-dt2.y);
            float w0 = dt2.x * u2.x,   w1 = dt2.y * u2.y;
            float p0 = e0, p1 = e1;
            float y0 = 0.f, y1 = 0.f;
#pragma unroll
            for (int s = 0; s < DS; s++) {
                float Bs = sBC[t * 32 + s];
                float Cs = sBC[t * 32 + 16 + s];
                h0[s] = fmaf(p0, h0[s], w0 * Bs);
                h1[s] = fmaf(p1, h1[s], w1 * Bs);
                y0 = fmaf(h0[s], Cs, y0);
                y1 = fmaf(h1[s], Cs, y1);
                p0 *= e0; p1 *= e1;
            }
            float2 z2 = *(const float2*)(zp + (size_t)t * (2 * DI));
            float o0 = (y0 + Dv.x * u2.x) * siluf(z2.x);
            float o1 = (y1 + Dv.y * u2.y) * siluf(z2.y);
            yp[(size_t)t * (DI / 2)] = __floats2bfloat162_rn(o0, o1);
        }
    } else {
        float a0[DS], a1[DS];
#pragma unroll
        for (int s = 0; s < DS; s++) {
            a0[s] = g_A[d0 * DS + s];
            a1[s] = g_A[(d0 + 1) * DS + s];
        }
        for (int t = 0; t < CH; t++) {
            float2 dt2 = *(const float2*)(dtp + (size_t)t * DI);
            float2 u2  = *(const float2*)(up  + (size_t)t * DI);
            float w0 = dt2.x * u2.x, w1 = dt2.y * u2.y;
            float y0 = 0.f, y1 = 0.f;
#pragma unroll
            for (int s = 0; s < DS; s++) {
                float Bs = sBC[t * 32 + s];
                float Cs = sBC[t * 32 + 16 + s];
                float dA0 = __expf(dt2.x * a0[s]);
                float dA1 = __expf(dt2.y * a1[s]);
                h0[s] = fmaf(dA0, h0[s], w0 * Bs);
                h1[s] = fmaf(dA1, h1[s], w1 * Bs);
                y0 = fmaf(h0[s], Cs, y0);
                y1 = fmaf(h1[s], Cs, y1);
            }
            float2 z2 = *(const float2*)(zp + (size_t)t * (2 * DI));
            float o0 = (y0 + Dv.x * u2.x) * siluf(z2.x);
            float o1 = (y1 + Dv.y * u2.y) * siluf(z2.y);
            yp[(size_t)t * (DI / 2)] = __floats2bfloat162_rn(o0, o1);
        }
    }
}

// ---------------- launcher ----------------
extern "C" void kernel_launch(void* const* d_in, const int* in_sizes, int n_in,
                              void* d_out, int out_size) {
    (void)in_sizes; (void)n_in; (void)out_size;
    const float* x          = (const float*)d_in[0];
    const float* norm_w     = (const float*)d_in[1];
    const float* in_proj_w  = (const float*)d_in[2];
    const float* conv_w     = (const float*)d_in[3];
    const float* conv_b     = (const float*)d_in[4];
    const float* x_proj_w   = (const float*)d_in[5];
    const float* dt_proj_w  = (const float*)d_in[6];
    const float* dt_proj_b  = (const float*)d_in[7];
    const float* A_log      = (const float*)d_in[8];
    const float* D_param    = (const float*)d_in[9];
    const float* out_proj_w = (const float*)d_in[10];
    float* out = (float*)d_out;

    float *p_xz, *p_u, *p_xdbl, *p_part, *p_dt;
    __nv_bfloat16 *p_xnb, *p_yb, *p_winb, *p_woutb;
    cudaGetSymbolAddress((void**)&p_xz,    g_xz);
    cudaGetSymbolAddress((void**)&p_u,     g_u);
    cudaGetSymbolAddress((void**)&p_xdbl,  g_xdbl);
    cudaGetSymbolAddress((void**)&p_part,  g_part);
    cudaGetSymbolAddress((void**)&p_dt,    g_dt);
    cudaGetSymbolAddress((void**)&p_xnb,   g_xnb);
    cudaGetSymbolAddress((void**)&p_yb,    g_yb);
    cudaGetSymbolAddress((void**)&p_winb,  g_winb);
    cudaGetSymbolAddress((void**)&p_woutb, g_woutb);

    cudaFuncSetAttribute(hgemm<0>, cudaFuncAttributeMaxDynamicSharedMemorySize, HG_SMEM);
    cudaFuncSetAttribute(hgemm<2>, cudaFuncAttributeMaxDynamicSharedMemorySize, HG_SMEM);

    k_init<<<1, 1>>>();
    k_prepA<<<(DI * DS + 255) / 256, 256>>>(A_log);
    k_rmsnorm<<<NTOK, 256>>>(x, norm_w);
    k_f2b<<<((2 * DI * DM / 4) + 255) / 256, 256>>>(in_proj_w, p_winb, 2 * DI * DM / 4);
    k_f2b<<<((DM * DI / 4) + 255) / 256, 256>>>(out_proj_w, p_woutb, DM * DI / 4);

    // xz = x_norm @ in_proj_w^T   [8192 x 4096]  -- bf16 mma.sync
    hgemm<0><<<dim3(2 * DI / 128, NTOK / 128), 256, HG_SMEM>>>(
        p_xnb, DM, p_winb, DM, p_xz, 2 * DI, DM, nullptr);

    // u = silu(conv1d(x_in) + b)
    k_conv<<<(NTOK * (DI / 4)) / 256, 256>>>(conv_w, conv_b);

    // x_dbl = u @ x_proj_w^T   [8192 x 96]  (split-K fp32)
    sgemm_kernel<0><<<dim3(1, NTOK / 128, NSPLIT), 256>>>(
        p_u, DI, x_proj_w, DI, p_part, PD, NTOK, PD, DI / NSPLIT,
        nullptr, (size_t)NTOK * PD);
    k_reduce_xdbl<<<(NTOK * PD) / 256, 256>>>();

    // dt = softplus(x_dbl[:, :64] @ dt_proj_w^T + b)   [8192 x 2048] fp32
    sgemm_kernel<1><<<dim3(DI / 128, NTOK / 128, 1), 256>>>(
        p_xdbl, PD, dt_proj_w, RK, p_dt, DI, NTOK, DI, RK, dt_proj_b, 0);

    // selective scan + fused (+D*u)*silu(z), y emitted as bf16
    k_scan1<<<dim3(DI / 256, BATCHN, NC), 128>>>();
    k_scan2<<<(BATCHN * DS * DI) / 256, 256>>>();
    k_scan3<<<dim3(DI / 256, BATCHN, NC), 128>>>(D_param);

    // out = x + y @ out_proj_w^T   [8192 x 1024]  -- bf16 mma.sync + residual
    hgemm<2><<<dim3(DM / 128, NTOK / 128), 256, HG_SMEM>>>(
        p_yb, DI, p_woutb, DI, out, DM, DI, x);
}

// round 12
// speedup vs baseline: 7.3039x; 1.2634x over previous
#include <cuda_runtime.h>
#include <cuda_bf16.h>
#include <math.h>
#include <stdint.h>

#define BATCHN 4
#define SEQL   2048
#define DM     1024
#define DI     2048
#define DS     16
#define RK     64
#define XDC    128             // padded x_dbl column count (96 -> 128)
#define NTOK   (BATCHN*SEQL)   // 8192
#define NC     32              // scan chunks
#define CH     64              // chunk length

// ---------------- scratch (static device allocation; no cudaMalloc) ----------
__device__ __align__(16) __nv_bfloat16 g_xzb [(size_t)NTOK*2*DI];   // 64 MB
__device__ __align__(16) __nv_bfloat16 g_ub  [(size_t)NTOK*DI];     // 32 MB
__device__ __align__(16) __nv_bfloat16 g_dtb [(size_t)NTOK*DI];     // 32 MB
__device__ __align__(16) float         g_xdbl[(size_t)NTOK*XDC];    // 4 MB (fp32 B,C)
__device__ __align__(16) __nv_bfloat16 g_xdblb[(size_t)NTOK*XDC];   // 2 MB (bf16 dt in)
__device__ __align__(16) __nv_bfloat16 g_yb  [(size_t)NTOK*DI];     // 32 MB
__device__ __align__(16) __nv_bfloat16 g_xnb [(size_t)NTOK*DM];     // 16 MB
__device__ __align__(16) __nv_bfloat16 g_winb[(size_t)2*DI*DM];     // 8 MB
__device__ __align__(16) __nv_bfloat16 g_woutb[(size_t)DM*DI];      // 4 MB
__device__ __align__(16) __nv_bfloat16 g_xpwb[(size_t)XDC*DI];      // padded x_proj_w
__device__ __align__(16) __nv_bfloat16 g_dtwb[(size_t)DI*RK];
__device__ float g_A    [DI*DS];
__device__ float g_hend  [(size_t)BATCHN*NC*DS*DI];
__device__ float g_P     [(size_t)BATCHN*NC*DS*DI];
__device__ float g_hstart[(size_t)BATCHN*NC*DS*DI];
__device__ int   g_fast = 1;

// ---------------- helpers ----------------
__device__ __forceinline__ float softplusf(float v) {
    return v > 20.0f ? v : log1pf(__expf(v));
}
__device__ __forceinline__ float siluf(float v) {
    return v / (1.0f + __expf(-v));
}
__device__ __forceinline__ uint32_t smem_u32(const void* p) {
    uint32_t a;
    asm("{ .reg .u64 t; cvta.to.shared.u64 t, %1; cvt.u32.u64 %0, t; }" : "=r"(a) : "l"(p));
    return a;
}
__device__ __forceinline__ void cp16(uint32_t sm, const void* g) {
    asm volatile("cp.async.cg.shared.global [%0], [%1], 16;" :: "r"(sm), "l"(g));
}
__device__ __forceinline__ void ldsm4(uint32_t* r, uint32_t addr) {
    asm volatile("ldmatrix.sync.aligned.m8n8.x4.shared.b16 {%0,%1,%2,%3}, [%4];"
        : "=r"(r[0]), "=r"(r[1]), "=r"(r[2]), "=r"(r[3]) : "r"(addr));
}
__device__ __forceinline__ void mma16816(float* c, const uint32_t* a, uint32_t b0, uint32_t b1) {
    asm volatile("mma.sync.aligned.m16n8k16.row.col.f32.bf16.bf16.f32 "
        "{%0,%1,%2,%3}, {%4,%5,%6,%7}, {%8,%9}, {%0,%1,%2,%3};"
        : "+f"(c[0]), "+f"(c[1]), "+f"(c[2]), "+f"(c[3])
        : "r"(a[0]), "r"(a[1]), "r"(a[2]), "r"(a[3]), "r"(b0), "r"(b1));
}
__device__ __forceinline__ uint32_t packbf2(float a, float b) {
    __nv_bfloat162 h = __floats2bfloat162_rn(a, b);
    return *(uint32_t*)&h;
}

// ---------------- bf16 HGEMM (mma.sync): acc fp32 = A[M,K]bf16 @ W[N,K]bf16^T
// 128x128 tile, BK=64 (128B swizzled rows), double-buffered cp.async.
// 8 warps 2(M)x4(N); warp tile 64x32.
// EPI 2: fp32 store + residual (EP = resid, same layout as C)
// EPI 3: bf16 store (C is bf16*)
// EPI 4: softplus(acc + EP[col]) -> bf16 store (C is bf16*)
// EPI 5: fp32 store (C) + bf16 copy (aux)
#define HG_SMEM 65536
template<int EPI>
__global__ __launch_bounds__(256, 2)
void hgemm(const __nv_bfloat16* __restrict__ A, int lda,
           const __nv_bfloat16* __restrict__ W, int ldw,
           void* __restrict__ Cv, int ldc, int K,
           const float* __restrict__ EP,
           __nv_bfloat16* __restrict__ aux)
{
    extern __shared__ char smem_raw[];
    const uint32_t abase = smem_u32(smem_raw);          // A bufs: 2 x 16KB
    const uint32_t bbase = abase + 32768;               // B bufs: 2 x 16KB
    const int tid = threadIdx.x, wid = tid >> 5, lane = tid & 31;
    const int mBase = blockIdx.y * 128, nBase = blockIdx.x * 128;
    const int warpM = (wid >> 2) * 64;   // 0 or 64
    const int warpN = (wid & 3) * 32;    // 0,32,64,96

    float acc[4][4][4];
#pragma unroll
    for (int i = 0; i < 4; i++)
#pragma unroll
        for (int j = 0; j < 4; j++)
#pragma unroll
            for (int q = 0; q < 4; q++) acc[i][j][q] = 0.f;

    const int nk = K / 64;

    auto load_stage = [&](int kt) {
        const int b = kt & 1;
        const uint32_t aB = abase + b * 16384;
        const uint32_t bB = bbase + b * 16384;
        const __nv_bfloat16* Ag = A + (size_t)mBase * lda + kt * 64;
        const __nv_bfloat16* Wg = W + (size_t)nBase * ldw + kt * 64;
#pragma unroll
        for (int p = 0; p < 4; p++) {
            int idx = p * 256 + tid;           // 0..1023
            int row = idx >> 3, u = idx & 7;
            int su = row * 8 + (u ^ (row & 7));
            cp16(aB + su * 16, Ag + (size_t)row * lda + u * 8);
            cp16(bB + su * 16, Wg + (size_t)row * ldw + u * 8);
        }
        asm volatile("cp.async.commit_group;" ::: "memory");
    };

    load_stage(0);
    for (int kt = 0; kt < nk; kt++) {
        if (kt + 1 < nk) {
            load_stage(kt + 1);
            asm volatile("cp.async.wait_group 1;" ::: "memory");
        } else {
            asm volatile("cp.async.wait_group 0;" ::: "memory");
        }
        __syncthreads();
        const int b = kt & 1;
        const uint32_t aB = abase + b * 16384;
        const uint32_t bB = bbase + b * 16384;
#pragma unroll
        for (int ks = 0; ks < 4; ks++) {
            uint32_t afr[4][4];
#pragma unroll
            for (int mt = 0; mt < 4; mt++) {
                int r = warpM + mt * 16 + (lane & 15);
                int u = ks * 2 + (lane >> 4);
                ldsm4(afr[mt], aB + (r * 8 + (u ^ (r & 7))) * 16);
            }
            uint32_t bfr[2][4];
#pragma unroll
            for (int nt = 0; nt < 2; nt++) {
                int r = warpN + nt * 16 + (lane & 15);
                int u = ks * 2 + (lane >> 4);
                ldsm4(bfr[nt], bB + (r * 8 + (u ^ (r & 7))) * 16);
            }
#pragma unroll
            for (int mt = 0; mt < 4; mt++)
#pragma unroll
                for (int j = 0; j < 4; j++)
                    mma16816(acc[mt][j], afr[mt], bfr[j >> 1][j & 1], bfr[j >> 1][(j & 1) + 2]);
        }
        __syncthreads();
    }

    // epilogue: c0,c1 -> (row=lane/4, col=2*(lane%4)+{0,1}); c2,c3 -> row+8
#pragma unroll
    for (int mt = 0; mt < 4; mt++) {
        const int row0 = mBase + warpM + mt * 16 + (lane >> 2);
        const int row1 = row0 + 8;
#pragma unroll
        for (int j = 0; j < 4; j++) {
            const int col = nBase + warpN + j * 8 + (lane & 3) * 2;
            float v00 = acc[mt][j][0], v01 = acc[mt][j][1];
            float v10 = acc[mt][j][2], v11 = acc[mt][j][3];
            if (EPI == 2) {
                float* C = (float*)Cv;
                float2 r0 = *(const float2*)&EP[(size_t)row0 * ldc + col];
                float2 r1 = *(const float2*)&EP[(size_t)row1 * ldc + col];
                *(float2*)&C[(size_t)row0 * ldc + col] = make_float2(v00 + r0.x, v01 + r0.y);
                *(float2*)&C[(size_t)row1 * ldc + col] = make_float2(v10 + r1.x, v11 + r1.y);
            } else if (EPI == 3) {
                __nv_bfloat16* C = (__nv_bfloat16*)Cv;
                *(uint32_t*)&C[(size_t)row0 * ldc + col] = packbf2(v00, v01);
                *(uint32_t*)&C[(size_t)row1 * ldc + col] = packbf2(v10, v11);
            } else if (EPI == 4) {
                __nv_bfloat16* C = (__nv_bfloat16*)Cv;
                float b0 = EP[col], b1 = EP[col + 1];
                *(uint32_t*)&C[(size_t)row0 * ldc + col] =
                    packbf2(softplusf(v00 + b0), softplusf(v01 + b1));
                *(uint32_t*)&C[(size_t)row1 * ldc + col] =
                    packbf2(softplusf(v10 + b0), softplusf(v11 + b1));
            } else if (EPI == 5) {
                float* C = (float*)Cv;
                *(float2*)&C[(size_t)row0 * ldc + col] = make_float2(v00, v01);
                *(float2*)&C[(size_t)row1 * ldc + col] = make_float2(v10, v11);
                *(uint32_t*)&aux[(size_t)row0 * ldc + col] = packbf2(v00, v01);
                *(uint32_t*)&aux[(size_t)row1 * ldc + col] = packbf2(v10, v11);
            }
        }
    }
}

// ---------------- prep ----------------
__global__ void k_prepA(const float* __restrict__ A_log) {
    int i = blockIdx.x * blockDim.x + threadIdx.x;
    if (i < DI * DS) {
        float a = -__expf(A_log[i]);
        g_A[i] = a;
        int s = i & (DS - 1);
        float expect = -(float)(s + 1);
        if (fabsf(a - expect) > 1e-3f * (float)(s + 1))
            atomicExch(&g_fast, 0);
    }
}

// fp32 -> bf16 conversion (n4 = n/4)
__global__ void k_f2b(const float* __restrict__ src, __nv_bfloat16* __restrict__ dst, int n4) {
    int i = blockIdx.x * blockDim.x + threadIdx.x;
    if (i < n4) {
        float4 v = ((const float4*)src)[i];
        uint2 o; o.x = packbf2(v.x, v.y); o.y = packbf2(v.z, v.w);
        ((uint2*)dst)[i] = o;
    }
}

// x_proj_w [96, DI] -> bf16 padded [128, DI] (rows 96..127 zero)
__global__ void k_padxw(const float* __restrict__ src) {
    int i = blockIdx.x * blockDim.x + threadIdx.x;   // over XDC*DI/4
    if (i >= XDC * (DI / 4)) return;
    int row = i / (DI / 4), cq = i % (DI / 4);
    uint2 o;
    if (row < 96) {
        float4 v = *(const float4*)&src[(size_t)row * DI + cq * 4];
        o.x = packbf2(v.x, v.y); o.y = packbf2(v.z, v.w);
    } else {
        o.x = 0u; o.y = 0u;
    }
    ((uint2*)g_xpwb)[i] = o;
}

// ---------------- RMSNorm -> bf16 ----------------
__global__ __launch_bounds__(256)
void k_rmsnorm(const float* __restrict__ x, const float* __restrict__ w) {
    int row = blockIdx.x;
    const float4* xr = reinterpret_cast<const float4*>(x) + (size_t)row * (DM / 4);
    float4 v = xr[threadIdx.x];
    float ss = v.x * v.x + v.y * v.y + v.z * v.z + v.w * v.w;
#pragma unroll
    for (int o = 16; o > 0; o >>= 1) ss += __shfl_xor_sync(0xffffffffu, ss, o);
    __shared__ float red[8];
    __shared__ float scale_s;
    int wid = threadIdx.x >> 5;
    if ((threadIdx.x & 31) == 0) red[wid] = ss;
    __syncthreads();
    if (threadIdx.x == 0) {
        float t = 0.f;
#pragma unroll
        for (int i = 0; i < 8; i++) t += red[i];
        scale_s = rsqrtf(t * (1.0f / (float)DM) + 1.1920929e-7f);
    }
    __syncthreads();
    float s = scale_s;
    float4 wv = reinterpret_cast<const float4*>(w)[threadIdx.x];
    uint2 o;
    o.x = packbf2(v.x * s * wv.x, v.y * s * wv.y);
    o.y = packbf2(v.z * s * wv.z, v.w * s * wv.w);
    ((uint2*)g_xnb)[(size_t)row * (DM / 4) + threadIdx.x] = o;
}

// ---------------- causal depthwise conv1d + SiLU (bf16 in/out, fp32 math) ----
__global__ void k_conv(const float* __restrict__ cw, const float* __restrict__ cb) {
    int i = blockIdx.x * blockDim.x + threadIdx.x;
    if (i >= NTOK * (DI / 4)) return;
    int dq = i % (DI / 4);
    int t  = i / (DI / 4);
    int d4 = dq * 4;
    int b = t >> 11, l = t & (SEQL - 1);
    float4 acc = *(const float4*)&cb[d4];
    float wreg[4][4];
#pragma unroll
    for (int r = 0; r < 4; r++) {
        float4 wr = *(const float4*)&cw[(d4 + r) * 4];
        wreg[r][0] = wr.x; wreg[r][1] = wr.y; wreg[r][2] = wr.z; wreg[r][3] = wr.w;
    }
#pragma unroll
    for (int j = 0; j < 4; j++) {
        int lj = l - 3 + j;
        if (lj >= 0) {
            uint2 xv = *(const uint2*)&g_xzb[(size_t)(b * SEQL + lj) * (2 * DI) + d4];
            float2 x01 = __bfloat1622float2(*(__nv_bfloat162*)&xv.x);
            float2 x23 = __bfloat1622float2(*(__nv_bfloat162*)&xv.y);
            acc.x = fmaf(x01.x, wreg[0][j], acc.x);
            acc.y = fmaf(x01.y, wreg[1][j], acc.y);
            acc.z = fmaf(x23.x, wreg[2][j], acc.z);
            acc.w = fmaf(x23.y, wreg[3][j], acc.w);
        }
    }
    uint2 o;
    o.x = packbf2(siluf(acc.x), siluf(acc.y));
    o.y = packbf2(siluf(acc.z), siluf(acc.w));
    *(uint2*)&g_ub[(size_t)t * DI + d4] = o;
}

// ---------------- scan phase 1: per-chunk local recurrence (h0=0) ------------
__global__ __launch_bounds__(128)
void k_scan1() {
    __shared__ float sBC[CH * 32];
    const int b = blockIdx.y, c = blockIdx.z;
    const int l0 = c * CH;
    const int tid = threadIdx.x;
    for (int i = tid; i < CH * 8; i += 128) {
        int r = i >> 3, cq = i & 7;
        *(float4*)&sBC[r * 32 + cq * 4] =
            *(const float4*)&g_xdbl[(size_t)(b * SEQL + l0 + r) * XDC + 64 + cq * 4];
    }
    __syncthreads();
    const int d0 = blockIdx.x * 256 + tid * 2;
    float h0[DS], h1[DS];
#pragma unroll
    for (int s = 0; s < DS; s++) { h0[s] = 0.f; h1[s] = 0.f; }
    const __nv_bfloat162* dtp =
        (const __nv_bfloat162*)&g_dtb[(size_t)(b * SEQL + l0) * DI + d0];
    const __nv_bfloat162* up =
        (const __nv_bfloat162*)&g_ub[(size_t)(b * SEQL + l0) * DI + d0];
    const size_t sb = (size_t)(b * NC + c) * DS * DI + d0;
    const int fast = g_fast;

    if (fast) {
        float q0 = 1.f, q1 = 1.f;
        for (int t = 0; t < CH; t++) {
            float2 dt2 = __bfloat1622float2(dtp[(size_t)t * (DI / 2)]);
            float2 u2  = __bfloat1622float2(up[(size_t)t * (DI / 2)]);
            float e0 = __expf(-dt2.x), e1 = __expf(-dt2.y);
            float w0 = dt2.x * u2.x,   w1 = dt2.y * u2.y;
            q0 *= e0; q1 *= e1;
            float p0 = e0, p1 = e1;
#pragma unroll
            for (int s = 0; s < DS; s++) {
                float Bs = sBC[t * 32 + s];
                h0[s] = fmaf(p0, h0[s], w0 * Bs);
                h1[s] = fmaf(p1, h1[s], w1 * Bs);
                p0 *= e0; p1 *= e1;
            }
        }
#pragma unroll
        for (int s = 0; s < DS; s++)
            *(float2*)&g_hend[sb + (size_t)s * DI] = make_float2(h0[s], h1[s]);
        float pp0 = q0, pp1 = q1;
#pragma unroll
        for (int s = 0; s < DS; s++) {
            *(float2*)&g_P[sb + (size_t)s * DI] = make_float2(pp0, pp1);
            pp0 *= q0; pp1 *= q1;
        }
    } else {
        float a0[DS], a1[DS], P0[DS], P1[DS];
#pragma unroll
        for (int s = 0; s < DS; s++) {
            a0[s] = g_A[d0 * DS + s];
            a1[s] = g_A[(d0 + 1) * DS + s];
            P0[s] = 1.f; P1[s] = 1.f;
        }
        for (int t = 0; t < CH; t++) {
            float2 dt2 = __bfloat1622float2(dtp[(size_t)t * (DI / 2)]);
            float2 u2  = __bfloat1622float2(up[(size_t)t * (DI / 2)]);
            float w0 = dt2.x * u2.x, w1 = dt2.y * u2.y;
#pragma unroll
            for (int s = 0; s < DS; s++) {
                float Bs = sBC[t * 32 + s];
                float dA0 = __expf(dt2.x * a0[s]);
                float dA1 = __expf(dt2.y * a1[s]);
                h0[s] = fmaf(dA0, h0[s], w0 * Bs);
                h1[s] = fmaf(dA1, h1[s], w1 * Bs);
                P0[s] *= dA0; P1[s] *= dA1;
            }
        }
#pragma unroll
        for (int s = 0; s < DS; s++) {
            *(float2*)&g_hend[sb + (size_t)s * DI] = make_float2(h0[s], h1[s]);
            *(float2*)&g_P  [sb + (size_t)s * DI] = make_float2(P0[s], P1[s]);
        }
    }
}

// ---------------- scan phase 2: combine chunk states ----------------
__global__ void k_scan2() {
    int idx = blockIdx.x * blockDim.x + threadIdx.x;
    if (idx >= BATCHN * DS * DI) return;
    int d = idx & (DI - 1);
    int s = (idx >> 11) & (DS - 1);
    int b = idx >> 15;
    float hs = 0.f;
    size_t base = ((size_t)(b * NC) * DS + s) * DI + d;
    const size_t cstride = (size_t)DS * DI;
    for (int c = 0; c < NC; c++) {
        size_t off = base + (size_t)c * cstride;
        g_hstart[off] = hs;
        hs = g_P[off] * hs + g_hend[off];
    }
}

// ---------------- scan phase 3: recompute with correct h0, emit y bf16 -------
__global__ __launch_bounds__(128)
void k_scan3(const float* __restrict__ Dp_) {
    __shared__ float sBC[CH * 32];
    const int b = blockIdx.y, c = blockIdx.z;
    const int l0 = c * CH;
    const int tid = threadIdx.x;
    for (int i = tid; i < CH * 8; i += 128) {
        int r = i >> 3, cq = i & 7;
        *(float4*)&sBC[r * 32 + cq * 4] =
            *(const float4*)&g_xdbl[(size_t)(b * SEQL + l0 + r) * XDC + 64 + cq * 4];
    }
    __syncthreads();
    const int d0 = blockIdx.x * 256 + tid * 2;
    const size_t sb = (size_t)(b * NC + c) * DS * DI + d0;
    float h0[DS], h1[DS];
#pragma unroll
    for (int s = 0; s < DS; s++) {
        float2 hv = *(const float2*)&g_hstart[sb + (size_t)s * DI];
        h0[s] = hv.x; h1[s] = hv.y;
    }
    float2 Dv = *(const float2*)&Dp_[d0];
    const __nv_bfloat162* dtp =
        (const __nv_bfloat162*)&g_dtb[(size_t)(b * SEQL + l0) * DI + d0];
    const __nv_bfloat162* up =
        (const __nv_bfloat162*)&g_ub[(size_t)(b * SEQL + l0) * DI + d0];
    const __nv_bfloat162* zp =
        (const __nv_bfloat162*)&g_xzb[(size_t)(b * SEQL + l0) * (2 * DI) + DI + d0];
    __nv_bfloat162* yp = (__nv_bfloat162*)&g_yb[(size_t)(b * SEQL + l0) * DI + d0];
    const int fast = g_fast;

    if (fast) {
        for (int t = 0; t < CH; t++) {
            float2 dt2 = __bfloat1622float2(dtp[(size_t)t * (DI / 2)]);
            float2 u2  = __bfloat1622float2(up[(size_t)t * (DI / 2)]);
            float e0 = __expf(-dt2.x), e1 = __expf(-dt2.y);
            float w0 = dt2.x * u2.x,   w1 = dt2.y * u2.y;
            float p0 = e0, p1 = e1;
            float y0 = 0.f, y1 = 0.f;
#pragma unroll
            for (int s = 0; s < DS; s++) {
                float Bs = sBC[t * 32 + s];
                float Cs = sBC[t * 32 + 16 + s];
                h0[s] = fmaf(p0, h0[s], w0 * Bs);
                h1[s] = fmaf(p1, h1[s], w1 * Bs);
                y0 = fmaf(h0[s], Cs, y0);
                y1 = fmaf(h1[s], Cs, y1);
                p0 *= e0; p1 *= e1;
            }
            float2 z2 = __bfloat1622float2(zp[(size_t)t * DI]);
            float o0 = (y0 + Dv.x * u2.x) * siluf(z2.x);
            float o1 = (y1 + Dv.y * u2.y) * siluf(z2.y);
            yp[(size_t)t * (DI / 2)] = __floats2bfloat162_rn(o0, o1);
        }
    } else {
        float a0[DS], a1[DS];
#pragma unroll
        for (int s = 0; s < DS; s++) {
            a0[s] = g_A[d0 * DS + s];
            a1[s] = g_A[(d0 + 1) * DS + s];
        }
        for (int t = 0; t < CH; t++) {
            float2 dt2 = __bfloat1622float2(dtp[(size_t)t * (DI / 2)]);
            float2 u2  = __bfloat1622float2(up[(size_t)t * (DI / 2)]);
            float w0 = dt2.x * u2.x, w1 = dt2.y * u2.y;
            float y0 = 0.f, y1 = 0.f;
#pragma unroll
            for (int s = 0; s < DS; s++) {
                float Bs = sBC[t * 32 + s];
                float Cs = sBC[t * 32 + 16 + s];
                float dA0 = __expf(dt2.x * a0[s]);
                float dA1 = __expf(dt2.y * a1[s]);
                h0[s] = fmaf(dA0, h0[s], w0 * Bs);
                h1[s] = fmaf(dA1, h1[s], w1 * Bs);
                y0 = fmaf(h0[s], Cs, y0);
                y1 = fmaf(h1[s], Cs, y1);
            }
            float2 z2 = __bfloat1622float2(zp[(size_t)t * DI]);
            float o0 = (y0 + Dv.x * u2.x) * siluf(z2.x);
            float o1 = (y1 + Dv.y * u2.y) * siluf(z2.y);
            yp[(size_t)t * (DI / 2)] = __floats2bfloat162_rn(o0, o1);
        }
    }
}

// ---------------- launcher ----------------
extern "C" void kernel_launch(void* const* d_in, const int* in_sizes, int n_in,
                              void* d_out, int out_size) {
    (void)in_sizes; (void)n_in; (void)out_size;
    const float* x          = (const float*)d_in[0];
    const float* norm_w     = (const float*)d_in[1];
    const float* in_proj_w  = (const float*)d_in[2];
    const float* conv_w     = (const float*)d_in[3];
    const float* conv_b     = (const float*)d_in[4];
    const float* x_proj_w   = (const float*)d_in[5];
    const float* dt_proj_w  = (const float*)d_in[6];
    const float* dt_proj_b  = (const float*)d_in[7];
    const float* A_log      = (const float*)d_in[8];
    const float* D_param    = (const float*)d_in[9];
    const float* out_proj_w = (const float*)d_in[10];
    float* out = (float*)d_out;

    __nv_bfloat16 *p_xzb, *p_ub, *p_dtb, *p_xdblb, *p_yb, *p_xnb;
    __nv_bfloat16 *p_winb, *p_woutb, *p_xpwb, *p_dtwb;
    float *p_xdbl;
    cudaGetSymbolAddress((void**)&p_xzb,   g_xzb);
    cudaGetSymbolAddress((void**)&p_ub,    g_ub);
    cudaGetSymbolAddress((void**)&p_dtb,   g_dtb);
    cudaGetSymbolAddress((void**)&p_xdbl,  g_xdbl);
    cudaGetSymbolAddress((void**)&p_xdblb, g_xdblb);
    cudaGetSymbolAddress((void**)&p_yb,    g_yb);
    cudaGetSymbolAddress((void**)&p_xnb,   g_xnb);
    cudaGetSymbolAddress((void**)&p_winb,  g_winb);
    cudaGetSymbolAddress((void**)&p_woutb, g_woutb);
    cudaGetSymbolAddress((void**)&p_xpwb,  g_xpwb);
    cudaGetSymbolAddress((void**)&p_dtwb,  g_dtwb);

    cudaFuncSetAttribute(hgemm<2>, cudaFuncAttributeMaxDynamicSharedMemorySize, HG_SMEM);
    cudaFuncSetAttribute(hgemm<3>, cudaFuncAttributeMaxDynamicSharedMemorySize, HG_SMEM);
    cudaFuncSetAttribute(hgemm<4>, cudaFuncAttributeMaxDynamicSharedMemorySize, HG_SMEM);
    cudaFuncSetAttribute(hgemm<5>, cudaFuncAttributeMaxDynamicSharedMemorySize, HG_SMEM);

    k_prepA<<<(DI * DS + 255) / 256, 256>>>(A_log);
    k_rmsnorm<<<NTOK, 256>>>(x, norm_w);
    k_f2b<<<((2 * DI * DM / 4) + 255) / 256, 256>>>(in_proj_w, p_winb, 2 * DI * DM / 4);
    k_f2b<<<((DM * DI / 4) + 255) / 256, 256>>>(out_proj_w, p_woutb, DM * DI / 4);
    k_f2b<<<((DI * RK / 4) + 255) / 256, 256>>>(dt_proj_w, p_dtwb, DI * RK / 4);
    k_padxw<<<((XDC * DI / 4) + 255) / 256, 256>>>(x_proj_w);

    // xz = x_norm @ in_proj_w^T   [8192 x 4096] bf16 out
    hgemm<3><<<dim3(2 * DI / 128, NTOK / 128), 256, HG_SMEM>>>(
        p_xnb, DM, p_winb, DM, p_xzb, 2 * DI, DM, nullptr, nullptr);

    // u = silu(conv1d(x_in) + b)   bf16 out
    k_conv<<<(NTOK * (DI / 4)) / 256, 256>>>(conv_w, conv_b);

    // x_dbl = u @ x_proj_w^T   [8192 x 128(pad)]  fp32 + bf16 copy
    hgemm<5><<<dim3(1, NTOK / 128), 256, HG_SMEM>>>(
        p_ub, DI, p_xpwb, DI, p_xdbl, XDC, DI, nullptr, p_xdblb);

    // dt = softplus(x_dbl[:, :64] @ dt_proj_w^T + b)   [8192 x 2048] bf16 out
    hgemm<4><<<dim3(DI / 128, NTOK / 128), 256, HG_SMEM>>>(
        p_xdblb, XDC, p_dtwb, RK, p_dtb, DI, RK, dt_proj_b, nullptr);

    // selective scan + fused (+D*u)*silu(z)
    k_scan1<<<dim3(DI / 256, BATCHN, NC), 128>>>();
    k_scan2<<<(BATCHN * DS * DI) / 256, 256>>>();
    k_scan3<<<dim3(DI / 256, BATCHN, NC), 128>>>(D_param);

    // out = x + y @ out_proj_w^T   [8192 x 1024]  fp32 + residual
    hgemm<2><<<dim3(DM / 128, NTOK / 128), 256, HG_SMEM>>>(
        p_yb, DI, p_woutb, DI, out, DM, DI, x, nullptr);
}